// round 15
// baseline (speedup 1.0000x reference)
#include <cuda_runtime.h>
#include <cuda_bf16.h>

// Problem constants (fixed by the reference)
#define Cc    8
#define Ll    4096
#define Ff    32
#define Kk    10
#define PROC  20
#define STEP  5
#define NWIN  815          // == CHAN_OUT
#define WPB   288          // threads per block (9 warps); 3 windows/thread
#define WINPB 864          // window slots per block (covers all 815)
#define NCH   3            // windows (chains) per thread
#define SPAN  (PROC + (NCH - 1) * STEP)  // 30-sample span covering 3 windows
#define FPB   2            // filters per block (f and f+16), rolled loop
#define FGRID (Ff / FPB)   // 16

// Shared x tile: covers WINPB windows -> WINPB*STEP + (PROC-STEP) = 4335 floats
#define SXN (WINPB * STEP + PROC - STEP)

// Exact 3-way float min for NONNEGATIVE floats via DPX (single VIMNMX3):
// IEEE nonneg floats order identically to their int bit patterns.
__device__ __forceinline__ float fmin3_nonneg(float a, float b, float c)
{
    return __int_as_float(__vimin3_s32(__float_as_int(a),
                                       __float_as_int(b),
                                       __float_as_int(c)));
}

// One chain's cell update at window-local column J (compile-time) with df.
#define CHAIN_CELL(ACC, DG, J, DF)                                             \
    do {                                                                       \
        if ((J) == 0) {                                                        \
            DG = ACC[0];                                                       \
            ACC[0] = fmaf((DF), (DF), ACC[0]);                                 \
        } else {                                                               \
            const float _up = ACC[(J)];                                        \
            const float _m  = fmin3_nonneg(ACC[(J) - 1], _up, DG);             \
            ACC[(J)] = fmaf((DF), (DF), _m);                                   \
            DG = _up;                                                          \
        }                                                                      \
    } while (0)

#define CHAIN_CELL0(ACC, J, DF)                                                \
    do {                                                                       \
        ACC[(J)] = ((J) == 0) ? (DF) * (DF) : fmaf((DF), (DF), ACC[(J) - 1]);  \
    } while (0)

__global__ __launch_bounds__(WPB, 2)
void dtw_kernel(const float* __restrict__ x,
                const float* __restrict__ kernels,
                float* __restrict__ out)
{
    const int fp  = blockIdx.x;           // filter pair [0, 16): f = fp, fp+16
    const int bc  = blockIdx.y;           // b*C + c [0, 64)
    const int tid = threadIdx.x;

    __shared__ float sx[SXN];

    // Vectorized fill: 1024 float4s cover [0, 4096); zero-fill the 239-float tail.
    const float4* xc4 = (const float4*)(x + (size_t)bc * Ll);
    #pragma unroll
    for (int i = tid; i < Ll / 4; i += WPB) {
        *reinterpret_cast<float4*>(&sx[i * 4]) = xc4[i];
    }
    if (Ll + tid < SXN) sx[Ll + tid] = 0.0f;
    __syncthreads();

    // This thread owns adjacent windows g0 = 3*tid, g0+1, g0+2.
    const int g0 = NCH * tid;
    if (g0 >= NWIN) return;               // 16 threads exit; no syncs below

    const int sbase = g0 * STEP;          // stride 15: gcd(15,32)=1, no conflicts

    // Rolled loop over the block's two filters (I$-friendly; no FP state
    // crosses the boundary so no rotation-MOV cost).
    #pragma unroll 1
    for (int ff = 0; ff < FPB; ff++) {
        const int f = fp + ff * FGRID;

        // Kernel taps: warp-uniform addresses -> broadcast loads, L1-resident
        float ker[Kk];
        #pragma unroll
        for (int i = 0; i < Kk; i++) ker[i] = __ldg(&kernels[f * Kk + i]);

        // Three DTW tables: w0 = span[0..19], w1 = span[5..24], w2 = span[10..29].
        // df computed ONCE per span position feeds all three chains; chains are
        // staggered by 5 columns -> three independent MIN3->FFMA pipelines.
        float a0[PROC], a1[PROC], a2[PROC];

        // Row 0: cumulative sum of squared diffs
        {
            const float k0 = ker[0];
            #pragma unroll
            for (int jj = 0; jj < SPAN; jj++) {
                const float df = k0 - sx[sbase + jj];
                if (jj < PROC)                          CHAIN_CELL0(a0, jj,            df);
                if (jj >= STEP && jj < PROC + STEP)     CHAIN_CELL0(a1, jj - STEP,     df);
                if (jj >= 2 * STEP)                     CHAIN_CELL0(a2, jj - 2 * STEP, df);
            }
        }

        // Rows 1..K-1: DPX 3-way min; serial path per cell = VIMNMX3 + FFMA.
        #pragma unroll
        for (int i = 1; i < Kk; i++) {
            const float kv = ker[i];
            float dg0 = 0.0f, dg1 = 0.0f, dg2 = 0.0f;  // diag carries (init dead)
            #pragma unroll
            for (int jj = 0; jj < SPAN; jj++) {
                const float df = kv - sx[sbase + jj];
                if (jj < PROC)                          CHAIN_CELL(a0, dg0, jj,            df);
                if (jj >= STEP && jj < PROC + STEP)     CHAIN_CELL(a1, dg1, jj - STEP,     df);
                if (jj >= 2 * STEP)                     CHAIN_CELL(a2, dg2, jj - 2 * STEP, df);
            }
        }

        // out[b, c*F + f, w]: three adjacent elements per thread
        const size_t o = ((size_t)bc * Ff + f) * NWIN + g0;
        out[o] = a0[PROC - 1];
        if (g0 + 1 < NWIN) out[o + 1] = a1[PROC - 1];
        if (g0 + 2 < NWIN) out[o + 2] = a2[PROC - 1];
    }
}

extern "C" void kernel_launch(void* const* d_in, const int* in_sizes, int n_in,
                              void* d_out, int out_size)
{
    const float* x       = (const float*)d_in[0];   // (8, 8, 4096) f32
    const float* kernels = (const float*)d_in[1];   // (32, 10) f32
    float*       out     = (float*)d_out;           // (8, 256, 815) f32

    (void)in_sizes; (void)n_in; (void)out_size;

    dim3 grid(FGRID, 8 * Cc);   // (16, 64) -> 1024 blocks
    dtw_kernel<<<grid, WPB>>>(x, kernels, out);
}

// round 16
// speedup vs baseline: 1.3167x; 1.3167x over previous
#include <cuda_runtime.h>
#include <cuda_bf16.h>

// Problem constants (fixed by the reference)
#define Cc    8
#define Ll    4096
#define Ff    32
#define Kk    10
#define PROC  20
#define STEP  5
#define NWIN  815          // == CHAN_OUT
#define WPB   416          // threads per block (13 warps); 2 windows/thread
#define WINPB 832          // window slots per block (covers all 815)
#define SPAN  (PROC + STEP) // 25-sample span covering both windows
#define FPB   2            // filters per block (f and f+16), rolled loop
#define FGRID (Ff / FPB)   // 16

// Shared x tile: covers WINPB windows -> WINPB*STEP + (PROC-STEP) = 4175 floats
#define SXN (WINPB * STEP + PROC - STEP)

// Exact 3-way float min for NONNEGATIVE floats via DPX (single VIMNMX3):
// IEEE nonneg floats order identically to their int bit patterns.
__device__ __forceinline__ float fmin3_nonneg(float a, float b, float c)
{
    return __int_as_float(__vimin3_s32(__float_as_int(a),
                                       __float_as_int(b),
                                       __float_as_int(c)));
}

// Packed f32x2 helpers (Blackwell packed-FP32 pipe; ptxas never auto-fuses).
__device__ __forceinline__ unsigned long long pack2(float lo, float hi)
{
    unsigned long long r;
    asm("mov.b64 %0, {%1, %2};" : "=l"(r) : "f"(lo), "f"(hi));
    return r;
}
// (a + b) on both packed halves; halves come back as scalar regs (renamed).
__device__ __forceinline__ float2 add2(unsigned long long a, unsigned long long b)
{
    unsigned long long r;
    asm("add.rn.f32x2 %0, %1, %2;" : "=l"(r) : "l"(a), "l"(b));
    float lo, hi;
    asm("mov.b64 {%0, %1}, %2;" : "=f"(lo), "=f"(hi) : "l"(r));
    return make_float2(lo, hi);
}

// One DTW cell-pair update at span position JJ (compile-time) with shared df.
// df sign is irrelevant: used only as df*df.
#define DO_CELL(JJ, DF)                                                        \
    do {                                                                       \
        const float _df = (DF);                                                \
        if ((JJ) < PROC) {                                                     \
            if ((JJ) == 0) {                                                   \
                dg0 = a0[0];                                                   \
                a0[0] = fmaf(_df, _df, a0[0]);                                 \
            } else {                                                           \
                const float up = a0[(JJ)];                                     \
                const float m  = fmin3_nonneg(a0[(JJ) - 1], up, dg0);          \
                a0[(JJ)] = fmaf(_df, _df, m);                                  \
                dg0 = up;                                                      \
            }                                                                  \
        }                                                                      \
        if ((JJ) >= STEP) {                                                    \
            const int _j1 = (JJ) - STEP;                                       \
            if (_j1 == 0) {                                                    \
                dg1 = a1[0];                                                   \
                a1[0] = fmaf(_df, _df, a1[0]);                                 \
            } else {                                                           \
                const float up = a1[_j1];                                      \
                const float m  = fmin3_nonneg(a1[_j1 - 1], up, dg1);           \
                a1[_j1] = fmaf(_df, _df, m);                                   \
                dg1 = up;                                                      \
            }                                                                  \
        }                                                                      \
    } while (0)

// Row-0 (cumsum) variant
#define DO_CELL0(JJ, DF)                                                       \
    do {                                                                       \
        const float _df = (DF);                                                \
        if ((JJ) < PROC)                                                       \
            a0[(JJ)] = ((JJ) == 0) ? _df * _df : fmaf(_df, _df, a0[(JJ) - 1]); \
        if ((JJ) >= STEP) {                                                    \
            const int _j1 = (JJ) - STEP;                                       \
            a1[_j1] = (_j1 == 0) ? _df * _df : fmaf(_df, _df, a1[_j1 - 1]);    \
        }                                                                      \
    } while (0)

__global__ __launch_bounds__(WPB, 2)
void dtw_kernel(const float* __restrict__ x,
                const float* __restrict__ kernels,
                float* __restrict__ out)
{
    const int fp  = blockIdx.x;           // filter pair [0, 16): f = fp, fp+16
    const int bc  = blockIdx.y;           // b*C + c [0, 64)
    const int tid = threadIdx.x;

    __shared__ float sx[SXN];

    // Vectorized fill: 1024 float4s cover [0, 4096); zero-fill the 79-float tail.
    const float4* xc4 = (const float4*)(x + (size_t)bc * Ll);
    #pragma unroll
    for (int i = tid; i < Ll / 4; i += WPB) {
        *reinterpret_cast<float4*>(&sx[i * 4]) = xc4[i];
    }
    if (Ll + tid < SXN) sx[Ll + tid] = 0.0f;
    __syncthreads();

    // This thread owns adjacent windows g0 = 2*tid and g0+1.
    const int g0 = 2 * tid;
    if (g0 >= NWIN) return;               // only 8 threads exit; no syncs below

    const int sbase = g0 * STEP;          // = 10*tid: EVEN -> float2-aligned

    // Rolled loop over the block's two filters (I$-friendly; no FP state
    // crosses the boundary so no rotation-MOV cost).
    #pragma unroll 1
    for (int ff = 0; ff < FPB; ff++) {
        const int f = fp + ff * FGRID;

        // Kernel taps: warp-uniform addresses -> broadcast loads, L1-resident
        float ker[Kk];
        #pragma unroll
        for (int i = 0; i < Kk; i++) ker[i] = __ldg(&kernels[f * Kk + i]);

        // Two DTW tables: w0 = span[0..19], w1 = span[5..24].
        // Per span pair: one LDS.64 + one packed ADD2 computes BOTH diffs
        // (s - kv; sign irrelevant under squaring): 12 ADD2 replace 24 FADD.
        float a0[PROC], a1[PROC];

        // Row 0: cumulative sum of squared diffs
        {
            const float kv = ker[0];
            const unsigned long long nkv = pack2(-kv, -kv);
            #pragma unroll
            for (int p = 0; p < SPAN / 2; p++) {
                const float2 sp = *reinterpret_cast<const float2*>(&sx[sbase + 2 * p]);
                const float2 d  = add2(pack2(sp.x, sp.y), nkv);
                DO_CELL0(2 * p,     d.x);
                DO_CELL0(2 * p + 1, d.y);
            }
            DO_CELL0(SPAN - 1, sx[sbase + SPAN - 1] - kv);
        }

        // Rows 1..K-1: DPX 3-way min; serial path per cell = VIMNMX3 + FFMA;
        // the two windows' chains are staggered by 5 columns. Fully unrolled.
        #pragma unroll
        for (int i = 1; i < Kk; i++) {
            const float kv = ker[i];
            const unsigned long long nkv = pack2(-kv, -kv);
            float dg0 = 0.0f, dg1 = 0.0f; // diag carries (init dead)
            #pragma unroll
            for (int p = 0; p < SPAN / 2; p++) {
                const float2 sp = *reinterpret_cast<const float2*>(&sx[sbase + 2 * p]);
                const float2 d  = add2(pack2(sp.x, sp.y), nkv);
                DO_CELL(2 * p,     d.x);
                DO_CELL(2 * p + 1, d.y);
            }
            DO_CELL(SPAN - 1, sx[sbase + SPAN - 1] - kv);
        }

        // out[b, c*F + f, w]: coalesced in w (two adjacent elements/thread)
        const size_t o = ((size_t)bc * Ff + f) * NWIN + g0;
        out[o] = a0[PROC - 1];
        if (g0 + 1 < NWIN) out[o + 1] = a1[PROC - 1];
    }
}

extern "C" void kernel_launch(void* const* d_in, const int* in_sizes, int n_in,
                              void* d_out, int out_size)
{
    const float* x       = (const float*)d_in[0];   // (8, 8, 4096) f32
    const float* kernels = (const float*)d_in[1];   // (32, 10) f32
    float*       out     = (float*)d_out;           // (8, 256, 815) f32

    (void)in_sizes; (void)n_in; (void)out_size;

    dim3 grid(FGRID, 8 * Cc);   // (16, 64) -> 1024 blocks
    dtw_kernel<<<grid, WPB>>>(x, kernels, out);
}